// round 1
// baseline (speedup 1.0000x reference)
#include <cuda_runtime.h>
#include <cuda_bf16.h>
#include <cstdio>

#define N_NODES 50000
#define N_EDGES 800000
#define N_GRAPHS 2048
#define HID 128
#define IN_DIM 7

// ------------------- scratch (device globals; no allocation) -------------------
__device__ float g_agg[N_NODES * HID];    // aggregation buffer (layer1 uses first N*7)
__device__ float g_hpre[N_NODES * HID];   // pre-BN features
__device__ float g_h1[N_NODES * HID];     // post-BN/ReLU features
__device__ float g_stats[2 * HID];        // column sum, sumsq
__device__ float g_scale[HID];
__device__ float g_shift[HID];
__device__ float g_pooled[N_GRAPHS * HID];
__device__ float g_cnt[N_GRAPHS];

// ------------------- utility -------------------
__global__ void zero_kernel(float* __restrict__ p, int n4) {
    int i = blockIdx.x * blockDim.x + threadIdx.x;
    if (i < n4) reinterpret_cast<float4*>(p)[i] = make_float4(0.f, 0.f, 0.f, 0.f);
}

// ------------------- layer-1 edge message (d = 7) -------------------
__global__ void edge_kernel7(const float* __restrict__ x, const float* __restrict__ ea,
                             const int* __restrict__ ei,
                             const float* __restrict__ We, const float* __restrict__ be) {
    __shared__ float sW[3 * IN_DIM];
    __shared__ float sb[IN_DIM];
    int tid = threadIdx.x;
    if (tid < 3 * IN_DIM) sW[tid] = We[tid];
    if (tid < IN_DIM) sb[tid] = be[tid];
    __syncthreads();
    int e = blockIdx.x * blockDim.x + tid;
    if (e >= N_EDGES) return;
    float a0 = ea[e * 3 + 0], a1 = ea[e * 3 + 1], a2 = ea[e * 3 + 2];
    int s = ei[e];
    int d = ei[N_EDGES + e];
    const float* xr = x + (size_t)s * IN_DIM;
    float* ag = g_agg + (size_t)d * IN_DIM;
#pragma unroll
    for (int j = 0; j < IN_DIM; j++) {
        float m = xr[j] + a0 * sW[j] + a1 * sW[IN_DIM + j] + a2 * sW[2 * IN_DIM + j] + sb[j];
        m = fmaxf(m, 0.f);
        atomicAdd(ag + j, m);
    }
}

// ------------------- edge message (d = 128), one warp per edge -------------------
__global__ void edge_kernel128(const float* __restrict__ h, const float* __restrict__ ea,
                               const int* __restrict__ ei,
                               const float* __restrict__ We, const float* __restrict__ be) {
    __shared__ float sWe[3 * HID];
    __shared__ float sbe[HID];
    int tid = threadIdx.x;
    for (int i = tid; i < 3 * HID; i += blockDim.x) sWe[i] = We[i];
    if (tid < HID) sbe[tid] = be[tid];
    __syncthreads();
    int warp = tid >> 5, lane = tid & 31;
    int e = blockIdx.x * 8 + warp;
    if (e >= N_EDGES) return;
    float v = (lane < 3) ? ea[e * 3 + lane] : 0.f;
    float a0 = __shfl_sync(0xffffffffu, v, 0);
    float a1 = __shfl_sync(0xffffffffu, v, 1);
    float a2 = __shfl_sync(0xffffffffu, v, 2);
    int s = ei[e];
    int d = ei[N_EDGES + e];
    int c = lane * 4;
    float4 x4 = *reinterpret_cast<const float4*>(h + (size_t)s * HID + c);
    float4 w0 = *reinterpret_cast<const float4*>(sWe + c);
    float4 w1 = *reinterpret_cast<const float4*>(sWe + HID + c);
    float4 w2 = *reinterpret_cast<const float4*>(sWe + 2 * HID + c);
    float4 b4 = *reinterpret_cast<const float4*>(sbe + c);
    float m0 = fmaxf(x4.x + a0 * w0.x + a1 * w1.x + a2 * w2.x + b4.x, 0.f);
    float m1 = fmaxf(x4.y + a0 * w0.y + a1 * w1.y + a2 * w2.y + b4.y, 0.f);
    float m2 = fmaxf(x4.z + a0 * w0.z + a1 * w1.z + a2 * w2.z + b4.z, 0.f);
    float m3 = fmaxf(x4.w + a0 * w0.w + a1 * w1.w + a2 * w2.w + b4.w, 0.f);
    float* ag = g_agg + (size_t)d * HID + c;
    atomicAdd(ag + 0, m0);
    atomicAdd(ag + 1, m1);
    atomicAdd(ag + 2, m2);
    atomicAdd(ag + 3, m3);
}

// ------------------- fused node MLP: hpre = relu((x+agg)@W1+b1)@W2+b2 ; BN stats -------------------
// 256 threads, 32 rows/block. Dynamic smem: sW[128*128] | As[32*K1] | Ts[32*128] | ssum[128] | ssq[128]
template <int K1>
__global__ void node_kernel(const float* __restrict__ x, const float* __restrict__ agg,
                            const float* __restrict__ W1, const float* __restrict__ b1,
                            const float* __restrict__ W2, const float* __restrict__ b2) {
    extern __shared__ float sm[];
    float* sW = sm;
    float* As = sm + HID * HID;
    float* Ts = As + 32 * K1;
    float* ssum = Ts + 32 * HID;
    float* ssq = ssum + HID;
    int tid = threadIdx.x;
    int base = blockIdx.x * 32;
    if (tid < HID) { ssum[tid] = 0.f; ssq[tid] = 0.f; }
    for (int i = tid; i < 32 * K1; i += 256) {
        int r = i / K1, k = i - r * K1;
        int row = base + r;
        As[i] = (row < N_NODES) ? (x[(size_t)row * K1 + k] + agg[(size_t)row * K1 + k]) : 0.f;
    }
    for (int i = tid; i < K1 * HID; i += 256) sW[i] = W1[i];
    __syncthreads();

    int jq = tid & 31;   // column quad -> cols 4*jq..4*jq+3
    int rq = tid >> 5;   // row quad    -> rows 4*rq..4*rq+3
    int c0 = jq * 4;
    float4 bb = *reinterpret_cast<const float4*>(b1 + c0);
    float acc[4][4];
#pragma unroll
    for (int i = 0; i < 4; i++) { acc[i][0] = bb.x; acc[i][1] = bb.y; acc[i][2] = bb.z; acc[i][3] = bb.w; }
    for (int k = 0; k < K1; k++) {
        float4 w = *reinterpret_cast<const float4*>(sW + k * HID + c0);
#pragma unroll
        for (int i = 0; i < 4; i++) {
            float a = As[(rq * 4 + i) * K1 + k];
            acc[i][0] += a * w.x; acc[i][1] += a * w.y; acc[i][2] += a * w.z; acc[i][3] += a * w.w;
        }
    }
    // relu -> Ts
#pragma unroll
    for (int i = 0; i < 4; i++) {
        float4 t = make_float4(fmaxf(acc[i][0], 0.f), fmaxf(acc[i][1], 0.f),
                               fmaxf(acc[i][2], 0.f), fmaxf(acc[i][3], 0.f));
        *reinterpret_cast<float4*>(Ts + (rq * 4 + i) * HID + c0) = t;
    }
    __syncthreads();  // sW reads done, Ts written
    for (int i = tid; i < HID * HID; i += 256) sW[i] = W2[i];
    __syncthreads();

    float4 bb2 = *reinterpret_cast<const float4*>(b2 + c0);
#pragma unroll
    for (int i = 0; i < 4; i++) { acc[i][0] = bb2.x; acc[i][1] = bb2.y; acc[i][2] = bb2.z; acc[i][3] = bb2.w; }
    for (int k = 0; k < HID; k++) {
        float4 w = *reinterpret_cast<const float4*>(sW + k * HID + c0);
#pragma unroll
        for (int i = 0; i < 4; i++) {
            float a = Ts[(rq * 4 + i) * HID + k];
            acc[i][0] += a * w.x; acc[i][1] += a * w.y; acc[i][2] += a * w.z; acc[i][3] += a * w.w;
        }
    }
    float cs[4] = {0.f, 0.f, 0.f, 0.f}, cq[4] = {0.f, 0.f, 0.f, 0.f};
#pragma unroll
    for (int i = 0; i < 4; i++) {
        int row = base + rq * 4 + i;
        if (row < N_NODES) {
            float4 o = make_float4(acc[i][0], acc[i][1], acc[i][2], acc[i][3]);
            *reinterpret_cast<float4*>(g_hpre + (size_t)row * HID + c0) = o;
#pragma unroll
            for (int c = 0; c < 4; c++) { cs[c] += acc[i][c]; cq[c] += acc[i][c] * acc[i][c]; }
        }
    }
#pragma unroll
    for (int c = 0; c < 4; c++) {
        atomicAdd(&ssum[c0 + c], cs[c]);
        atomicAdd(&ssq[c0 + c], cq[c]);
    }
    __syncthreads();
    if (tid < HID) {
        atomicAdd(&g_stats[tid], ssum[tid]);
        atomicAdd(&g_stats[HID + tid], ssq[tid]);
    }
}

// ------------------- BN finalize (1 block, 128 threads) -------------------
__global__ void bn_finalize(const float* __restrict__ gamma, const float* __restrict__ beta) {
    int t = threadIdx.x;
    float invN = 1.f / (float)N_NODES;
    float mu = g_stats[t] * invN;
    float var = g_stats[HID + t] * invN - mu * mu;
    float rs = rsqrtf(var + 1e-5f);
    float sc = gamma[t] * rs;
    g_scale[t] = sc;
    g_shift[t] = beta[t] - mu * sc;
}

// ------------------- BN apply + relu -------------------
__global__ void bn_apply(int n4) {
    int i = blockIdx.x * blockDim.x + threadIdx.x;
    if (i >= n4) return;
    float4 v = reinterpret_cast<const float4*>(g_hpre)[i];
    int c = (i * 4) & (HID - 1);
    v.x = fmaxf(v.x * g_scale[c + 0] + g_shift[c + 0], 0.f);
    v.y = fmaxf(v.y * g_scale[c + 1] + g_shift[c + 1], 0.f);
    v.z = fmaxf(v.z * g_scale[c + 2] + g_shift[c + 2], 0.f);
    v.w = fmaxf(v.w * g_scale[c + 3] + g_shift[c + 3], 0.f);
    reinterpret_cast<float4*>(g_h1)[i] = v;
}

// ------------------- global mean pool (sum + count), warp per node -------------------
__global__ void pool_kernel(const int* __restrict__ batch) {
    int gwarp = (blockIdx.x * blockDim.x + threadIdx.x) >> 5;
    int lane = threadIdx.x & 31;
    if (gwarp >= N_NODES) return;
    int g = batch[gwarp];
    float4 v = *reinterpret_cast<const float4*>(g_h1 + (size_t)gwarp * HID + lane * 4);
    float* p = g_pooled + (size_t)g * HID + lane * 4;
    atomicAdd(p + 0, v.x);
    atomicAdd(p + 1, v.y);
    atomicAdd(p + 2, v.z);
    atomicAdd(p + 3, v.w);
    if (lane == 0) atomicAdd(&g_cnt[g], 1.0f);
}

// ------------------- head: out = relu(pooled@Wf1+bf1)@Wf2+bf2 -------------------
__global__ void head_kernel(const float* __restrict__ Wf1, const float* __restrict__ bf1,
                            const float* __restrict__ Wf2, const float* __restrict__ bf2,
                            float* __restrict__ out) {
    __shared__ float p[HID];
    __shared__ float red[64];
    int g = blockIdx.x;
    int tid = threadIdx.x;  // 64 threads
    float c = fmaxf(g_cnt[g], 1.0f);
    float invc = 1.f / c;
    p[tid] = g_pooled[(size_t)g * HID + tid] * invc;
    p[tid + 64] = g_pooled[(size_t)g * HID + tid + 64] * invc;
    __syncthreads();
    float acc = bf1[tid];
    for (int k = 0; k < HID; k++) acc += p[k] * Wf1[k * 64 + tid];
    red[tid] = fmaxf(acc, 0.f) * Wf2[tid];
    __syncthreads();
    for (int s = 32; s > 0; s >>= 1) {
        if (tid < s) red[tid] += red[tid + s];
        __syncthreads();
    }
    if (tid == 0) out[g] = red[0] + bf2[0];
}

// ------------------- launch -------------------
extern "C" void kernel_launch(void* const* d_in, const int* in_sizes, int n_in,
                              void* d_out, int out_size) {
    const float* x = (const float*)d_in[0];
    const float* ea = (const float*)d_in[1];
    const int* ei = (const int*)d_in[2];
    const int* batch = (const int*)d_in[3];
    const float* We1 = (const float*)d_in[4];  const float* be1 = (const float*)d_in[5];
    const float* W11 = (const float*)d_in[6];  const float* b11 = (const float*)d_in[7];
    const float* W12 = (const float*)d_in[8];  const float* b12 = (const float*)d_in[9];
    const float* gm1 = (const float*)d_in[10]; const float* bt1 = (const float*)d_in[11];
    const float* We2 = (const float*)d_in[12]; const float* be2 = (const float*)d_in[13];
    const float* W21 = (const float*)d_in[14]; const float* b21 = (const float*)d_in[15];
    const float* W22 = (const float*)d_in[16]; const float* b22 = (const float*)d_in[17];
    const float* gm2 = (const float*)d_in[18]; const float* bt2 = (const float*)d_in[19];
    const float* We3 = (const float*)d_in[20]; const float* be3 = (const float*)d_in[21];
    const float* W31 = (const float*)d_in[22]; const float* b31 = (const float*)d_in[23];
    const float* W32 = (const float*)d_in[24]; const float* b32 = (const float*)d_in[25];
    const float* gm3 = (const float*)d_in[26]; const float* bt3 = (const float*)d_in[27];
    const float* Wf1 = (const float*)d_in[28]; const float* bf1 = (const float*)d_in[29];
    const float* Wf2 = (const float*)d_in[30]; const float* bf2 = (const float*)d_in[31];
    float* out = (float*)d_out;

    float *p_agg, *p_stats, *p_pooled, *p_cnt;
    cudaGetSymbolAddress((void**)&p_agg, g_agg);
    cudaGetSymbolAddress((void**)&p_stats, g_stats);
    cudaGetSymbolAddress((void**)&p_pooled, g_pooled);
    cudaGetSymbolAddress((void**)&p_cnt, g_cnt);
    float *p_h1, *p_hpre;
    cudaGetSymbolAddress((void**)&p_h1, g_h1);
    cudaGetSymbolAddress((void**)&p_hpre, g_hpre);

    const int SMEM7 = (HID * HID + 32 * IN_DIM + 32 * HID + 2 * HID) * 4;
    const int SMEM128 = (HID * HID + 32 * HID + 32 * HID + 2 * HID) * 4;
    cudaFuncSetAttribute(node_kernel<IN_DIM>, cudaFuncAttributeMaxDynamicSharedMemorySize, SMEM7);
    cudaFuncSetAttribute(node_kernel<HID>, cudaFuncAttributeMaxDynamicSharedMemorySize, SMEM128);

    const int nodeBlocks = (N_NODES + 31) / 32;   // 1563
    const int nh4 = N_NODES * HID / 4;            // 1.6M float4

    // ---------- layer 1 (d=7 message) ----------
    zero_kernel<<<(N_NODES * IN_DIM / 4 + 255) / 256, 256>>>(p_agg, N_NODES * IN_DIM / 4);
    zero_kernel<<<1, 64>>>(p_stats, 2 * HID / 4);
    edge_kernel7<<<(N_EDGES + 255) / 256, 256>>>(x, ea, ei, We1, be1);
    node_kernel<IN_DIM><<<nodeBlocks, 256, SMEM7>>>(x, p_agg, W11, b11, W12, b12);
    bn_finalize<<<1, HID>>>(gm1, bt1);
    bn_apply<<<(nh4 + 255) / 256, 256>>>(nh4);

    // ---------- layer 2 ----------
    zero_kernel<<<(nh4 + 255) / 256, 256>>>(p_agg, nh4);
    zero_kernel<<<1, 64>>>(p_stats, 2 * HID / 4);
    edge_kernel128<<<(N_EDGES + 7) / 8, 256>>>(p_h1, ea, ei, We2, be2);
    node_kernel<HID><<<nodeBlocks, 256, SMEM128>>>(p_h1, p_agg, W21, b21, W22, b22);
    bn_finalize<<<1, HID>>>(gm2, bt2);
    bn_apply<<<(nh4 + 255) / 256, 256>>>(nh4);

    // ---------- layer 3 ----------
    zero_kernel<<<(nh4 + 255) / 256, 256>>>(p_agg, nh4);
    zero_kernel<<<1, 64>>>(p_stats, 2 * HID / 4);
    edge_kernel128<<<(N_EDGES + 7) / 8, 256>>>(p_h1, ea, ei, We3, be3);
    node_kernel<HID><<<nodeBlocks, 256, SMEM128>>>(p_h1, p_agg, W31, b31, W32, b32);
    bn_finalize<<<1, HID>>>(gm3, bt3);
    bn_apply<<<(nh4 + 255) / 256, 256>>>(nh4);

    // ---------- pool + head ----------
    zero_kernel<<<(N_GRAPHS * HID / 4 + 255) / 256, 256>>>(p_pooled, N_GRAPHS * HID / 4);
    zero_kernel<<<1, N_GRAPHS / 4>>>(p_cnt, N_GRAPHS / 4);
    pool_kernel<<<(N_NODES * 32 + 255) / 256, 256>>>(batch);
    head_kernel<<<N_GRAPHS, 64>>>(Wf1, bf1, Wf2, bf2, out);
}

// round 2
// speedup vs baseline: 1.6375x; 1.6375x over previous
#include <cuda_runtime.h>
#include <cuda_bf16.h>
#include <cstdio>

#define N_NODES 50000
#define N_EDGES 800000
#define N_GRAPHS 2048
#define HID 128
#define IN_DIM 7
#define AGG7_STRIDE 8

// ------------------- scratch (device globals; no allocation) -------------------
__device__ float g_agg[N_NODES * HID];    // aggregation buffer (layer1 uses stride-8 rows)
__device__ float g_hpre[N_NODES * HID];   // pre-BN features
__device__ float g_h1[N_NODES * HID];     // post-BN/ReLU features
__device__ float g_stats[2 * HID];        // column sum, sumsq
__device__ float g_scale[HID];
__device__ float g_shift[HID];
__device__ float g_pooled[N_GRAPHS * HID];
__device__ float g_cnt[N_GRAPHS];

__device__ __forceinline__ void red_add_v4(float* addr, float a, float b, float c, float d) {
    asm volatile("red.global.add.v4.f32 [%0], {%1,%2,%3,%4};"
                 :: "l"(addr), "f"(a), "f"(b), "f"(c), "f"(d) : "memory");
}

// ------------------- utility -------------------
__global__ void zero_kernel(float* __restrict__ p, int n4) {
    int i = blockIdx.x * blockDim.x + threadIdx.x;
    if (i < n4) reinterpret_cast<float4*>(p)[i] = make_float4(0.f, 0.f, 0.f, 0.f);
}

// zero pooled + cnt + stats in one launch
__global__ void zero_misc() {
    int i = blockIdx.x * blockDim.x + threadIdx.x;
    if (i < N_GRAPHS * HID / 4)
        reinterpret_cast<float4*>(g_pooled)[i] = make_float4(0.f, 0.f, 0.f, 0.f);
    if (i < 2 * HID) g_stats[i] = 0.f;
    if (i < N_GRAPHS) g_cnt[i] = 0.f;
}

// ------------------- layer-1 edge message (d = 7, agg stride 8, vector red) -------------------
__global__ void edge_kernel7(const float* __restrict__ x, const float* __restrict__ ea,
                             const int* __restrict__ ei,
                             const float* __restrict__ We, const float* __restrict__ be) {
    __shared__ float sW[3 * IN_DIM];
    __shared__ float sb[IN_DIM];
    int tid = threadIdx.x;
    if (tid < 3 * IN_DIM) sW[tid] = We[tid];
    if (tid < IN_DIM) sb[tid] = be[tid];
    __syncthreads();
    int e = blockIdx.x * blockDim.x + tid;
    if (e >= N_EDGES) return;
    float a0 = ea[e * 3 + 0], a1 = ea[e * 3 + 1], a2 = ea[e * 3 + 2];
    int s = ei[e];
    int d = ei[N_EDGES + e];
    const float* xr = x + (size_t)s * IN_DIM;
    float m[8];
#pragma unroll
    for (int j = 0; j < IN_DIM; j++) {
        float v = xr[j] + a0 * sW[j] + a1 * sW[IN_DIM + j] + a2 * sW[2 * IN_DIM + j] + sb[j];
        m[j] = fmaxf(v, 0.f);
    }
    m[7] = 0.f;
    float* ag = g_agg + (size_t)d * AGG7_STRIDE;
    red_add_v4(ag, m[0], m[1], m[2], m[3]);
    red_add_v4(ag + 4, m[4], m[5], m[6], m[7]);
}

// ------------------- edge message (d = 128): warp per edge, 4 edges/warp, vector red ----------
#define EPW 4
__global__ void edge_kernel128(const float* __restrict__ h, const float* __restrict__ ea,
                               const int* __restrict__ ei,
                               const float* __restrict__ We, const float* __restrict__ be) {
    __shared__ float sWe[3 * HID];
    __shared__ float sbe[HID];
    int tid = threadIdx.x;
    for (int i = tid; i < 3 * HID; i += blockDim.x) sWe[i] = We[i];
    if (tid < HID) sbe[tid] = be[tid];
    __syncthreads();
    int warp = tid >> 5, lane = tid & 31;
    int c = lane * 4;
    float4 w0 = *reinterpret_cast<const float4*>(sWe + c);
    float4 w1 = *reinterpret_cast<const float4*>(sWe + HID + c);
    float4 w2 = *reinterpret_cast<const float4*>(sWe + 2 * HID + c);
    float4 b4 = *reinterpret_cast<const float4*>(sbe + c);
    int ebase = (blockIdx.x * 8 + warp) * EPW;
#pragma unroll
    for (int j = 0; j < EPW; j++) {
        int e = ebase + j;
        if (e >= N_EDGES) return;
        float v = (lane < 3) ? ea[e * 3 + lane] : 0.f;
        float a0 = __shfl_sync(0xffffffffu, v, 0);
        float a1 = __shfl_sync(0xffffffffu, v, 1);
        float a2 = __shfl_sync(0xffffffffu, v, 2);
        int s = ei[e];
        int d = ei[N_EDGES + e];
        float4 x4 = *reinterpret_cast<const float4*>(h + (size_t)s * HID + c);
        float m0 = fmaxf(x4.x + a0 * w0.x + a1 * w1.x + a2 * w2.x + b4.x, 0.f);
        float m1 = fmaxf(x4.y + a0 * w0.y + a1 * w1.y + a2 * w2.y + b4.y, 0.f);
        float m2 = fmaxf(x4.z + a0 * w0.z + a1 * w1.z + a2 * w2.z + b4.z, 0.f);
        float m3 = fmaxf(x4.w + a0 * w0.w + a1 * w1.w + a2 * w2.w + b4.w, 0.f);
        red_add_v4(g_agg + (size_t)d * HID + c, m0, m1, m2, m3);
    }
}

// ------------------- fused node MLP: hpre = relu((x+agg)@W1+b1)@W2+b2 ; BN stats -------------------
// 256 threads, 64 rows/block. smem: sW[128*128] | As[64*K1] | Ts[64*128] | ssum[128] | ssq[128]
template <int K1, int ASTR>
__global__ void node_kernel(const float* __restrict__ x, const float* __restrict__ agg,
                            const float* __restrict__ W1, const float* __restrict__ b1,
                            const float* __restrict__ W2, const float* __restrict__ b2) {
    extern __shared__ float sm[];
    float* sW = sm;
    float* As = sm + HID * HID;
    float* Ts = As + 64 * K1;
    float* ssum = Ts + 64 * HID;
    float* ssq = ssum + HID;
    int tid = threadIdx.x;
    int base = blockIdx.x * 64;
    if (tid < HID) { ssum[tid] = 0.f; ssq[tid] = 0.f; }
    for (int i = tid; i < 64 * K1; i += 256) {
        int r = i / K1, k = i - r * K1;
        int row = base + r;
        As[i] = (row < N_NODES) ? (x[(size_t)row * K1 + k] + agg[(size_t)row * ASTR + k]) : 0.f;
    }
    for (int i = tid; i < K1 * HID; i += 256) sW[i] = W1[i];
    __syncthreads();

    int jq = tid & 31;   // column quad -> cols 4*jq..4*jq+3
    int rg = tid >> 5;   // row group   -> rows rg*8..rg*8+7
    int c0 = jq * 4;
    const float* Ar = As + (size_t)(rg * 8) * K1;
    float acc[8][4];
    {
        float4 bb = *reinterpret_cast<const float4*>(b1 + c0);
#pragma unroll
        for (int i = 0; i < 8; i++) { acc[i][0] = bb.x; acc[i][1] = bb.y; acc[i][2] = bb.z; acc[i][3] = bb.w; }
    }
#pragma unroll 4
    for (int k = 0; k < K1; k++) {
        float4 w = *reinterpret_cast<const float4*>(sW + k * HID + c0);
#pragma unroll
        for (int i = 0; i < 8; i++) {
            float a = Ar[i * K1 + k];
            acc[i][0] += a * w.x; acc[i][1] += a * w.y; acc[i][2] += a * w.z; acc[i][3] += a * w.w;
        }
    }
#pragma unroll
    for (int i = 0; i < 8; i++) {
        float4 t = make_float4(fmaxf(acc[i][0], 0.f), fmaxf(acc[i][1], 0.f),
                               fmaxf(acc[i][2], 0.f), fmaxf(acc[i][3], 0.f));
        *reinterpret_cast<float4*>(Ts + (size_t)(rg * 8 + i) * HID + c0) = t;
    }
    __syncthreads();  // sW reads done, Ts written
    for (int i = tid; i < HID * HID; i += 256) sW[i] = W2[i];
    __syncthreads();

    {
        float4 bb2 = *reinterpret_cast<const float4*>(b2 + c0);
#pragma unroll
        for (int i = 0; i < 8; i++) { acc[i][0] = bb2.x; acc[i][1] = bb2.y; acc[i][2] = bb2.z; acc[i][3] = bb2.w; }
    }
    const float* Tr = Ts + (size_t)(rg * 8) * HID;
#pragma unroll 4
    for (int k = 0; k < HID; k++) {
        float4 w = *reinterpret_cast<const float4*>(sW + k * HID + c0);
#pragma unroll
        for (int i = 0; i < 8; i++) {
            float a = Tr[i * HID + k];
            acc[i][0] += a * w.x; acc[i][1] += a * w.y; acc[i][2] += a * w.z; acc[i][3] += a * w.w;
        }
    }
    float cs[4] = {0.f, 0.f, 0.f, 0.f}, cq[4] = {0.f, 0.f, 0.f, 0.f};
#pragma unroll
    for (int i = 0; i < 8; i++) {
        int row = base + rg * 8 + i;
        if (row < N_NODES) {
            float4 o = make_float4(acc[i][0], acc[i][1], acc[i][2], acc[i][3]);
            *reinterpret_cast<float4*>(g_hpre + (size_t)row * HID + c0) = o;
#pragma unroll
            for (int c = 0; c < 4; c++) { cs[c] += acc[i][c]; cq[c] += acc[i][c] * acc[i][c]; }
        }
    }
#pragma unroll
    for (int c = 0; c < 4; c++) {
        atomicAdd(&ssum[c0 + c], cs[c]);
        atomicAdd(&ssq[c0 + c], cq[c]);
    }
    __syncthreads();
    if (tid < HID) {
        atomicAdd(&g_stats[tid], ssum[tid]);
        atomicAdd(&g_stats[HID + tid], ssq[tid]);
    }
}

// ------------------- BN finalize (1 block, 128 threads); zeroes stats for next layer ----------
__global__ void bn_finalize(const float* __restrict__ gamma, const float* __restrict__ beta) {
    int t = threadIdx.x;
    float invN = 1.f / (float)N_NODES;
    float mu = g_stats[t] * invN;
    float var = g_stats[HID + t] * invN - mu * mu;
    float rs = rsqrtf(var + 1e-5f);
    float sc = gamma[t] * rs;
    g_scale[t] = sc;
    g_shift[t] = beta[t] - mu * sc;
    g_stats[t] = 0.f;
    g_stats[HID + t] = 0.f;
}

// ------------------- BN apply + relu; optionally zero agg buffer for next layer ----------
__global__ void bn_apply(int n4, float* __restrict__ aggz) {
    int i = blockIdx.x * blockDim.x + threadIdx.x;
    if (i >= n4) return;
    float4 v = reinterpret_cast<const float4*>(g_hpre)[i];
    int c = (i * 4) & (HID - 1);
    v.x = fmaxf(v.x * g_scale[c + 0] + g_shift[c + 0], 0.f);
    v.y = fmaxf(v.y * g_scale[c + 1] + g_shift[c + 1], 0.f);
    v.z = fmaxf(v.z * g_scale[c + 2] + g_shift[c + 2], 0.f);
    v.w = fmaxf(v.w * g_scale[c + 3] + g_shift[c + 3], 0.f);
    reinterpret_cast<float4*>(g_h1)[i] = v;
    if (aggz) reinterpret_cast<float4*>(aggz)[i] = make_float4(0.f, 0.f, 0.f, 0.f);
}

// ------------------- global mean pool (sum + count), warp per node, vector red ----------
__global__ void pool_kernel(const int* __restrict__ batch) {
    int gwarp = (blockIdx.x * blockDim.x + threadIdx.x) >> 5;
    int lane = threadIdx.x & 31;
    if (gwarp >= N_NODES) return;
    int g = batch[gwarp];
    float4 v = *reinterpret_cast<const float4*>(g_h1 + (size_t)gwarp * HID + lane * 4);
    red_add_v4(g_pooled + (size_t)g * HID + lane * 4, v.x, v.y, v.z, v.w);
    if (lane == 0) atomicAdd(&g_cnt[g], 1.0f);
}

// ------------------- head: out = relu(pooled@Wf1+bf1)@Wf2+bf2 -------------------
__global__ void head_kernel(const float* __restrict__ Wf1, const float* __restrict__ bf1,
                            const float* __restrict__ Wf2, const float* __restrict__ bf2,
                            float* __restrict__ out) {
    __shared__ float p[HID];
    __shared__ float red[64];
    int g = blockIdx.x;
    int tid = threadIdx.x;  // 64 threads
    float c = fmaxf(g_cnt[g], 1.0f);
    float invc = 1.f / c;
    p[tid] = g_pooled[(size_t)g * HID + tid] * invc;
    p[tid + 64] = g_pooled[(size_t)g * HID + tid + 64] * invc;
    __syncthreads();
    float acc = bf1[tid];
    for (int k = 0; k < HID; k++) acc += p[k] * Wf1[k * 64 + tid];
    red[tid] = fmaxf(acc, 0.f) * Wf2[tid];
    __syncthreads();
    for (int s = 32; s > 0; s >>= 1) {
        if (tid < s) red[tid] += red[tid + s];
        __syncthreads();
    }
    if (tid == 0) out[g] = red[0] + bf2[0];
}

// ------------------- launch -------------------
extern "C" void kernel_launch(void* const* d_in, const int* in_sizes, int n_in,
                              void* d_out, int out_size) {
    const float* x = (const float*)d_in[0];
    const float* ea = (const float*)d_in[1];
    const int* ei = (const int*)d_in[2];
    const int* batch = (const int*)d_in[3];
    const float* We1 = (const float*)d_in[4];  const float* be1 = (const float*)d_in[5];
    const float* W11 = (const float*)d_in[6];  const float* b11 = (const float*)d_in[7];
    const float* W12 = (const float*)d_in[8];  const float* b12 = (const float*)d_in[9];
    const float* gm1 = (const float*)d_in[10]; const float* bt1 = (const float*)d_in[11];
    const float* We2 = (const float*)d_in[12]; const float* be2 = (const float*)d_in[13];
    const float* W21 = (const float*)d_in[14]; const float* b21 = (const float*)d_in[15];
    const float* W22 = (const float*)d_in[16]; const float* b22 = (const float*)d_in[17];
    const float* gm2 = (const float*)d_in[18]; const float* bt2 = (const float*)d_in[19];
    const float* We3 = (const float*)d_in[20]; const float* be3 = (const float*)d_in[21];
    const float* W31 = (const float*)d_in[22]; const float* b31 = (const float*)d_in[23];
    const float* W32 = (const float*)d_in[24]; const float* b32 = (const float*)d_in[25];
    const float* gm3 = (const float*)d_in[26]; const float* bt3 = (const float*)d_in[27];
    const float* Wf1 = (const float*)d_in[28]; const float* bf1 = (const float*)d_in[29];
    const float* Wf2 = (const float*)d_in[30]; const float* bf2 = (const float*)d_in[31];
    float* out = (float*)d_out;

    float *p_agg;
    cudaGetSymbolAddress((void**)&p_agg, g_agg);

    const int SMEM7 = (HID * HID + 64 * IN_DIM + 64 * HID + 2 * HID) * 4;
    const int SMEM128 = (HID * HID + 64 * HID + 64 * HID + 2 * HID) * 4;
    cudaFuncSetAttribute(node_kernel<IN_DIM, AGG7_STRIDE>, cudaFuncAttributeMaxDynamicSharedMemorySize, SMEM7);
    cudaFuncSetAttribute(node_kernel<HID, HID>, cudaFuncAttributeMaxDynamicSharedMemorySize, SMEM128);

    const int nodeBlocks = (N_NODES + 63) / 64;   // 782
    const int nh4 = N_NODES * HID / 4;            // 1.6M float4
    const int edgeBlocks = (N_EDGES + 8 * EPW - 1) / (8 * EPW);  // 25000

    // ---------- init ----------
    zero_kernel<<<(N_NODES * AGG7_STRIDE / 4 + 255) / 256, 256>>>(p_agg, N_NODES * AGG7_STRIDE / 4);
    zero_misc<<<(N_GRAPHS * HID / 4 + 255) / 256, 256>>>();

    // ---------- layer 1 (d=7 message) ----------
    edge_kernel7<<<(N_EDGES + 255) / 256, 256>>>(x, ea, ei, We1, be1);
    node_kernel<IN_DIM, AGG7_STRIDE><<<nodeBlocks, 256, SMEM7>>>(x, p_agg, W11, b11, W12, b12);
    bn_finalize<<<1, HID>>>(gm1, bt1);
    bn_apply<<<(nh4 + 255) / 256, 256>>>(nh4, p_agg);   // also zero agg (128-stride) for layer 2

    // ---------- layer 2 ----------
    float *p_h1;
    cudaGetSymbolAddress((void**)&p_h1, g_h1);
    edge_kernel128<<<edgeBlocks, 256>>>(p_h1, ea, ei, We2, be2);
    node_kernel<HID, HID><<<nodeBlocks, 256, SMEM128>>>(p_h1, p_agg, W21, b21, W22, b22);
    bn_finalize<<<1, HID>>>(gm2, bt2);
    bn_apply<<<(nh4 + 255) / 256, 256>>>(nh4, p_agg);

    // ---------- layer 3 ----------
    edge_kernel128<<<edgeBlocks, 256>>>(p_h1, ea, ei, We3, be3);
    node_kernel<HID, HID><<<nodeBlocks, 256, SMEM128>>>(p_h1, p_agg, W31, b31, W32, b32);
    bn_finalize<<<1, HID>>>(gm3, bt3);
    bn_apply<<<(nh4 + 255) / 256, 256>>>(nh4, nullptr);

    // ---------- pool + head ----------
    pool_kernel<<<(N_NODES * 32 + 255) / 256, 256>>>(batch);
    head_kernel<<<N_GRAPHS, 64>>>(Wf1, bf1, Wf2, bf2, out);
}